// round 16
// baseline (speedup 1.0000x reference)
#include <cuda_runtime.h>
#include <stdint.h>

typedef unsigned long long u64;
typedef unsigned int u32;

#define NLEV 5
#define CLSN 16
#define TOPK 1000
#define NTOT 785664
#define HBITS 13
#define HB (1 << HBITS)        /* 8192 bins: ord >> 19 */
#define WCAP 4096
#define CHUNK 1536
#define NCHUNK 512             /* 512*1536 = 786432 >= NTOT */
#define XMASK 0xFFFFFFFF00000000ULL
#define MAXD 4.135166556742356f

__device__ __constant__ int d_off[6] = {0, 589824, 737280, 774144, 783360, 785664};
__device__ __constant__ int d_len[5] = {589824, 147456, 36864, 9216, 2304};

struct Ptrs {
    const float* anc[NLEV];
    const float* cls[NLEV];
    const float* reg[NLEV];
};

// ------- scratch (device globals; zero-initialized at load). Rotating
// cleanup: ruler zeroes g_cnt (select uses it later in the same call);
// select zeroes g_hist (resolve, which runs before select, consumed it);
// g_base / g_nwin / g_thr are fully overwritten by resolve each call. -------
__device__ int g_hist[NLEV * HB];
__device__ int g_cnt[NLEV * HB];
__device__ int g_base[NLEV * HB];
__device__ int g_nwin[NLEV];
__device__ u32 g_ord[NTOT];
__device__ u64 g_win[NLEV][WCAP];
__device__ int g_thr[NLEV];

__device__ __forceinline__ int level_of(int a) {
    int l = 0;
#pragma unroll
    for (int j = 1; j < NLEV; j++) l += (a >= d_off[j]);
    return l;
}

// ---- K1: ruler (max of 16 logits) + PRIVATE shared 13-bit histogram.
//      Also zeroes g_cnt for this call's select. ----
__global__ void __launch_bounds__(512)
k_ruler(Ptrs p) {
    __shared__ u32 h[HB];                     // 32 KB
    const int t = threadIdx.x;
    for (int b = t; b < HB; b += 512) h[b] = 0;
    {
        int g = blockIdx.x * 512 + t;
        if (g < NLEV * HB) g_cnt[g] = 0;
    }
    __syncthreads();

    const int cstart = blockIdx.x * CHUNK;
    const int l = level_of(cstart);
    const int base = d_off[l];
    const int iend = (cstart + CHUNK < NTOT) ? cstart + CHUNK : NTOT;
    const float4* cls4 = (const float4*)p.cls[l];

#pragma unroll
    for (int q = 0; q < 3; q++) {
        int a = cstart + q * 512 + t;
        if (a < iend) {
            int i = a - base;
            float4 va = cls4[i * 4 + 0], vb = cls4[i * 4 + 1];
            float4 vc = cls4[i * 4 + 2], vd = cls4[i * 4 + 3];
            float m = fmaxf(fmaxf(fmaxf(va.x, va.y), fmaxf(va.z, va.w)),
                            fmaxf(fmaxf(vb.x, vb.y), fmaxf(vb.z, vb.w)));
            m = fmaxf(m, fmaxf(fmaxf(vc.x, vc.y), fmaxf(vc.z, vc.w)));
            m = fmaxf(m, fmaxf(fmaxf(vd.x, vd.y), fmaxf(vd.z, vd.w)));
            u32 u = __float_as_uint(m);
            u32 ord = (u & 0x80000000u) ? ~u : (u | 0x80000000u);  // monotonic
            g_ord[a] = ord;
            atomicAdd(&h[ord >> (32 - HBITS)], 1u);
        }
    }
    __syncthreads();

    int* gh = &g_hist[l * HB];
    for (int b = t; b < HB; b += 512) {
        u32 c = h[b];
        if (c) atomicAdd(&gh[b], (int)c);     // <=384 adds per address
    }
}

// ---- K2: per-level threshold + per-bin rank bases + exact winner count.
//      base[b] = #elements in bins > b (their ranks precede bin b's). ----
__global__ void k_resolve() {
    const int l = blockIdx.x;
    const int t = threadIdx.x;                // 256 threads
    const int CH = HB / 256;                  // 32 bins/thread
    __shared__ int csum[256];
    const int* h = &g_hist[l * HB];
    int* gb = &g_base[l * HB];
    const int cb = t * CH;

    int s = 0;
#pragma unroll 4
    for (int j = 0; j < CH; j++) s += h[cb + j];
    csum[t] = s;
    __syncthreads();
    for (int off = 1; off < 256; off <<= 1) { // reversed scan -> suffix sums
        int v = csum[t];
        int add = (t + off < 256) ? csum[t + off] : 0;
        __syncthreads();
        csum[t] = v + add;
        __syncthreads();
    }
    const int sufnext = (t == 255) ? 0 : csum[t + 1];

    // write per-bin bases: base[cb+j] = sufnext + sum_{j' > j} h[cb+j']
    {
        int run = sufnext;
        for (int j = CH - 1; j >= 0; j--) {
            gb[cb + j] = run;
            run += h[cb + j];
        }
    }

    // threshold: largest bin b with suffix_count(b) >= TOPK; n = that count
    if (csum[t] >= TOPK && (t == 255 || csum[t + 1] < TOPK)) {
        int suf = sufnext, b = cb;
        for (int j = CH - 1; j >= 0; j--) {
            suf += h[cb + j];
            b = cb + j;
            if (suf >= TOPK) break;
        }
        g_thr[l] = b;
        g_nwin[l] = suf;                      // exact winner count
    }
}

// ---- K3: bucketized select: winner -> g_win[base[bin] + slot(bin)].
//      Result: g_win[l][0..n) densely packed, grouped by bin (desc).
//      Also zeroes g_hist for the next call (resolve already consumed it). ----
__global__ void __launch_bounds__(512)
k_select() {
    const int t = threadIdx.x;
    {
        int g = blockIdx.x * 512 + t;
        if (g < NLEV * HB) g_hist[g] = 0;
    }
    const int cstart = blockIdx.x * CHUNK;
    const int l = level_of(cstart);
    const int base = d_off[l];
    const int iend = (cstart + CHUNK < NTOT) ? cstart + CHUNK : NTOT;
    const u32 thr = (u32)g_thr[l];

#pragma unroll
    for (int q = 0; q < 3; q++) {
        int a = cstart + q * 512 + t;
        if (a < iend) {
            u32 ord = g_ord[a];
            u32 bin = ord >> (32 - HBITS);
            if (bin >= thr) {
                int slot = atomicAdd(&g_cnt[l * HB + bin], 1);
                int pos = g_base[l * HB + bin] + slot;
                if (pos < WCAP)
                    g_win[l][pos] = ((u64)ord << 32) | (u32)(a - base);
            }
        }
    }
}

// ---- K4: tiny within-bucket rank + emit. One winner per warp.
// rank(e) = base[bin(e)] + #{same-bucket keys < e} over unique keys
// (~ord, idx) == exact jax top_k position. Buckets are tiny (~1-10),
// so the scan is 1-2 global iterations; then the warp decodes the box
// and lanes 0..15 write the 16 output rows. No smem, no syncthreads. ----
__global__ void __launch_bounds__(256)
k_emit(Ptrs p, float* __restrict__ out) {
    const int l = blockIdx.y;
    const int warp = threadIdx.x >> 5;
    const int lane = threadIdx.x & 31;

    int n = g_nwin[l];
    int nn = (n < WCAP) ? n : WCAP;
    const int e = blockIdx.x * 8 + warp;
    if (blockIdx.x * 8 >= nn) return;         // whole block out of range
    if (e >= nn) return;

    const u64* win = g_win[l];
    const u64 raw = win[e];
    const u64 me = raw ^ XMASK;               // ascending (~ord, idx)
    const u32 ord = (u32)(raw >> 32);
    const int b = (int)(ord >> (32 - HBITS));

    const int start = g_base[l * HB + b];
    int end = (b > 0) ? g_base[l * HB + b - 1] : n;
    if (end > nn) end = nn;

    int cnt = 0;
    for (int j = start + lane; j < end; j += 32)
        cnt += ((win[j] ^ XMASK) < me);
    const int rank = start + __reduce_add_sync(0xFFFFFFFFu, cnt);
    if (rank >= TOPK) return;

    u32 idx = (u32)(raw & 0xFFFFFFFFu);
    if (idx >= (u32)d_len[l]) idx = 0;        // safety (never hit on valid data)

    // decode box once per warp (broadcast loads)
    float4 a4 = ((const float4*)p.anc[l])[idx];
    float4 r4 = ((const float4*)p.reg[l])[idx * 2];
    float w = a4.z - a4.x, h = a4.w - a4.y;
    float cx = a4.x + 0.5f * w, cy = a4.y + 0.5f * h;
    float pcx = cx + r4.x * w, pcy = cy + r4.y * h;
    float pw = w * expf(fminf(r4.z, MAXD));
    float ph = h * expf(fminf(r4.w, MAXD));
    float x0 = pcx - 0.5f * pw, y0 = pcy - 0.5f * ph;
    float x1 = pcx + 0.5f * pw, y1 = pcy + 0.5f * ph;

    if (lane < CLSN) {
        float score = p.cls[l][(size_t)idx * CLSN + lane];  // coalesced 64B
        float sg = 1.0f / (1.0f + expf(-score));
        float* lout = out + (size_t)l * TOPK * CLSN * 6;
        float2* o2 = (float2*)(lout + ((size_t)rank * CLSN + lane) * 6);
        o2[0] = make_float2(x0, y0);
        o2[1] = make_float2(x1, y1);
        o2[2] = make_float2(sg, (float)(lane + 1));
    }
}

extern "C" void kernel_launch(void* const* d_in, const int* in_sizes, int n_in,
                              void* d_out, int out_size) {
    (void)in_sizes; (void)n_in; (void)out_size;
    Ptrs p;
    for (int l = 0; l < NLEV; l++) {
        p.anc[l] = (const float*)d_in[3 * l + 0];
        p.cls[l] = (const float*)d_in[3 * l + 1];
        p.reg[l] = (const float*)d_in[3 * l + 2];
    }

    k_ruler<<<NCHUNK, 512>>>(p);
    k_resolve<<<NLEV, 256>>>();
    k_select<<<NCHUNK, 512>>>();
    dim3 ge(WCAP / 8, NLEV);
    k_emit<<<ge, 256>>>(p, (float*)d_out);
}

// round 17
// speedup vs baseline: 1.0845x; 1.0845x over previous
#include <cuda_runtime.h>
#include <stdint.h>

typedef unsigned long long u64;
typedef unsigned int u32;

#define NLEV 5
#define CLSN 16
#define TOPK 1000
#define NTOT 785664
#define KTOT (NLEV * TOPK)
#define HBITS 13
#define HB (1 << HBITS)        /* 8192 bins: ord >> 19 */
#define WCAP 4096
#define CHUNK 1536
#define NCHUNK 512             /* 512*1536 = 786432 >= NTOT */
#define XMASK 0xFFFFFFFF00000000ULL
#define MAXD 4.135166556742356f

__device__ __constant__ int d_off[6] = {0, 589824, 737280, 774144, 783360, 785664};
__device__ __constant__ int d_len[5] = {589824, 147456, 36864, 9216, 2304};

struct Ptrs {
    const float* anc[NLEV];
    const float* cls[NLEV];
    const float* reg[NLEV];
};

// ------- scratch (device globals; zero-initialized at load). Rotating
// cleanup: ruler zeroes g_cnt (select consumes it later this call);
// select zeroes g_hist (resolve already consumed it); g_base / g_nwin /
// g_thr / g_sel are fully (re)written every call. -------
__device__ int g_hist[NLEV * HB];
__device__ int g_cnt[NLEV * HB];
__device__ int g_base[NLEV * HB];
__device__ int g_nwin[NLEV];
__device__ u32 g_ord[NTOT];
__device__ u64 g_win[NLEV][WCAP];
__device__ int g_thr[NLEV];
__device__ u32 g_sel[KTOT];

__device__ __forceinline__ int level_of(int a) {
    int l = 0;
#pragma unroll
    for (int j = 1; j < NLEV; j++) l += (a >= d_off[j]);
    return l;
}

// ---- K1: ruler (max of 16 logits) + PRIVATE shared 13-bit histogram.
//      Also zeroes g_cnt for this call's select. ----
__global__ void __launch_bounds__(512)
k_ruler(Ptrs p) {
    __shared__ u32 h[HB];                     // 32 KB
    const int t = threadIdx.x;
    for (int b = t; b < HB; b += 512) h[b] = 0;
    {
        int g = blockIdx.x * 512 + t;
        if (g < NLEV * HB) g_cnt[g] = 0;
    }
    __syncthreads();

    const int cstart = blockIdx.x * CHUNK;
    const int l = level_of(cstart);
    const int base = d_off[l];
    const int iend = (cstart + CHUNK < NTOT) ? cstart + CHUNK : NTOT;
    const float4* cls4 = (const float4*)p.cls[l];

#pragma unroll
    for (int q = 0; q < 3; q++) {
        int a = cstart + q * 512 + t;
        if (a < iend) {
            int i = a - base;
            float4 va = cls4[i * 4 + 0], vb = cls4[i * 4 + 1];
            float4 vc = cls4[i * 4 + 2], vd = cls4[i * 4 + 3];
            float m = fmaxf(fmaxf(fmaxf(va.x, va.y), fmaxf(va.z, va.w)),
                            fmaxf(fmaxf(vb.x, vb.y), fmaxf(vb.z, vb.w)));
            m = fmaxf(m, fmaxf(fmaxf(vc.x, vc.y), fmaxf(vc.z, vc.w)));
            m = fmaxf(m, fmaxf(fmaxf(vd.x, vd.y), fmaxf(vd.z, vd.w)));
            u32 u = __float_as_uint(m);
            u32 ord = (u & 0x80000000u) ? ~u : (u | 0x80000000u);  // monotonic
            g_ord[a] = ord;
            atomicAdd(&h[ord >> (32 - HBITS)], 1u);
        }
    }
    __syncthreads();

    int* gh = &g_hist[l * HB];
    for (int b = t; b < HB; b += 512) {
        u32 c = h[b];
        if (c) atomicAdd(&gh[b], (int)c);     // <=384 adds per address
    }
}

// ---- K2: per-level threshold + per-bin rank bases + exact winner count.
//      base[b] = #elements in bins > b (their ranks precede bin b's). ----
__global__ void k_resolve() {
    const int l = blockIdx.x;
    const int t = threadIdx.x;                // 256 threads
    const int CH = HB / 256;                  // 32 bins/thread
    __shared__ int csum[256];
    const int* h = &g_hist[l * HB];
    int* gb = &g_base[l * HB];
    const int cb = t * CH;

    int s = 0;
#pragma unroll 4
    for (int j = 0; j < CH; j++) s += h[cb + j];
    csum[t] = s;
    __syncthreads();
    for (int off = 1; off < 256; off <<= 1) { // reversed scan -> suffix sums
        int v = csum[t];
        int add = (t + off < 256) ? csum[t + off] : 0;
        __syncthreads();
        csum[t] = v + add;
        __syncthreads();
    }
    const int sufnext = (t == 255) ? 0 : csum[t + 1];

    // per-bin bases: base[cb+j] = sufnext + sum_{j' > j} h[cb+j']
    {
        int run = sufnext;
        for (int j = CH - 1; j >= 0; j--) {
            gb[cb + j] = run;
            run += h[cb + j];
        }
    }

    // threshold: largest bin b with suffix_count(b) >= TOPK; n = that count
    if (csum[t] >= TOPK && (t == 255 || csum[t + 1] < TOPK)) {
        int suf = sufnext, b = cb;
        for (int j = CH - 1; j >= 0; j--) {
            suf += h[cb + j];
            b = cb + j;
            if (suf >= TOPK) break;
        }
        g_thr[l] = b;
        g_nwin[l] = suf;                      // exact winner count
    }
}

// ---- K3: bucketized select: winner -> g_win[base[bin] + slot(bin)].
//      g_win[l][0..n) comes out densely packed, grouped by bin (desc).
//      Also zeroes g_hist for the next call. ----
__global__ void __launch_bounds__(512)
k_select() {
    const int t = threadIdx.x;
    {
        int g = blockIdx.x * 512 + t;
        if (g < NLEV * HB) g_hist[g] = 0;
    }
    const int cstart = blockIdx.x * CHUNK;
    const int l = level_of(cstart);
    const int base = d_off[l];
    const int iend = (cstart + CHUNK < NTOT) ? cstart + CHUNK : NTOT;
    const u32 thr = (u32)g_thr[l];

#pragma unroll
    for (int q = 0; q < 3; q++) {
        int a = cstart + q * 512 + t;
        if (a < iend) {
            u32 ord = g_ord[a];
            u32 bin = ord >> (32 - HBITS);
            if (bin >= thr) {
                int slot = atomicAdd(&g_cnt[l * HB + bin], 1);
                int pos = g_base[l * HB + bin] + slot;
                if (pos < WCAP)
                    g_win[l][pos] = ((u64)ord << 32) | (u32)(a - base);
            }
        }
    }
}

// ---- K4: tiny within-bucket rank -> g_sel. One winner per warp.
// rank(e) = base[bin(e)] + #{same-bucket keys < e}; keys (~ord, idx)
// unique -> exact jax top_k position. Buckets are ~1-10 elements. ----
__global__ void __launch_bounds__(256)
k_rank() {
    const int l = blockIdx.y;
    const int warp = threadIdx.x >> 5;
    const int lane = threadIdx.x & 31;

    int n = g_nwin[l];
    int nn = (n < WCAP) ? n : WCAP;
    if (blockIdx.x * 8 >= nn) return;         // whole block out of range
    const int e = blockIdx.x * 8 + warp;
    if (e >= nn) return;

    const u64* win = g_win[l];
    const u64 raw = win[e];
    const u64 me = raw ^ XMASK;               // ascending (~ord, idx)
    const int b = (int)((u32)(raw >> 32) >> (32 - HBITS));

    const int start = g_base[l * HB + b];
    int end = (b > 0) ? g_base[l * HB + b - 1] : n;   // = start + hist[b]
    if (end > nn) end = nn;

    int cnt = 0;
    for (int j = start + lane; j < end; j += 32)
        cnt += ((win[j] ^ XMASK) < me);
    const int rank = start + __reduce_add_sync(0xFFFFFFFFu, cnt);

    if (lane == 0 && rank < TOPK) {
        u32 idx = (u32)(raw & 0xFFFFFFFFu);
        if (idx >= (u32)d_len[l]) idx = 0;    // safety (never hit on valid data)
        g_sel[l * TOPK + rank] = idx;
    }
}

// ---- K5: decode + emit, staged & coalesced (grid 125 x 5, 128 thr) ----
__global__ void __launch_bounds__(128)
k_emit(Ptrs p, float* __restrict__ out) {
    __shared__ float4 bbox[8];
    __shared__ u32 sidx[8];
    const int l = blockIdx.y;
    const int kloc = blockIdx.x * 8;
    const int t = threadIdx.x;

    if (t < 8) {
        u32 idx = g_sel[l * TOPK + kloc + t];
        if (idx >= (u32)d_len[l]) idx = 0;     // safety
        sidx[t] = idx;
        float4 a4 = ((const float4*)p.anc[l])[idx];
        float4 r4 = ((const float4*)p.reg[l])[idx * 2];
        float w = a4.z - a4.x, h = a4.w - a4.y;
        float cx = a4.x + 0.5f * w, cy = a4.y + 0.5f * h;
        float pcx = cx + r4.x * w, pcy = cy + r4.y * h;
        float pw = w * expf(fminf(r4.z, MAXD));
        float ph = h * expf(fminf(r4.w, MAXD));
        bbox[t] = make_float4(pcx - 0.5f * pw, pcy - 0.5f * ph,
                              pcx + 0.5f * pw, pcy + 0.5f * ph);
    }
    __syncthreads();

    const int k = t >> 4;          // 0..7
    const int c = t & 15;
    u32 idx = sidx[k];
    float score = p.cls[l][(size_t)idx * 16 + c];
    float sg = 1.0f / (1.0f + expf(-score));
    float4 b4 = bbox[k];
    float* o = out + ((size_t)(l * TOPK + kloc + k) * CLSN + c) * 6;
    float2* o2 = (float2*)o;
    o2[0] = make_float2(b4.x, b4.y);
    o2[1] = make_float2(b4.z, b4.w);
    o2[2] = make_float2(sg, (float)(c + 1));
}

extern "C" void kernel_launch(void* const* d_in, const int* in_sizes, int n_in,
                              void* d_out, int out_size) {
    (void)in_sizes; (void)n_in; (void)out_size;
    Ptrs p;
    for (int l = 0; l < NLEV; l++) {
        p.anc[l] = (const float*)d_in[3 * l + 0];
        p.cls[l] = (const float*)d_in[3 * l + 1];
        p.reg[l] = (const float*)d_in[3 * l + 2];
    }

    k_ruler<<<NCHUNK, 512>>>(p);
    k_resolve<<<NLEV, 256>>>();
    k_select<<<NCHUNK, 512>>>();
    dim3 gr(WCAP / 8, NLEV);
    k_rank<<<gr, 256>>>();
    dim3 ge(TOPK / 8, NLEV);
    k_emit<<<ge, 128>>>(p, (float*)d_out);
}